// round 1
// baseline (speedup 1.0000x reference)
#include <cuda_runtime.h>

// Problem geometry (fixed by the reference):
//   inputs: float32 [16, 64, 256, 256]  (N, C, H, W), NCHW contiguous
//   per-channel count Nc = 16*256*256 = 1,048,576
//   HW = 65536 floats per (n,c) slice = 16384 float4
#define NB        16
#define NC        64
#define HW4       16384              // float4 per (n,c) slice
#define PERCHAN4  (NB * HW4)         // 262144 float4 per channel
#define TOTAL4    (NB * NC * HW4)    // 16,777,216 float4 total
#define EPS       1e-5f

__device__ float g_sum[NC];
__device__ float g_sq[NC];
__device__ float g_mean[NC];
__device__ float g_rstd[NC];

__global__ void zero_acc_kernel() {
    int t = threadIdx.x;
    if (t < NC) { g_sum[t] = 0.0f; g_sq[t] = 0.0f; }
}

// One channel per blockIdx.y; blockIdx.x chunks the channel's float4 space.
__global__ void reduce_kernel(const float4* __restrict__ in) {
    const int c = blockIdx.y;
    float s = 0.0f, q = 0.0f;

    const int stride = gridDim.x * blockDim.x;
    for (int j = blockIdx.x * blockDim.x + threadIdx.x; j < PERCHAN4; j += stride) {
        const int n   = j >> 14;       // j / HW4
        const int hw4 = j & (HW4 - 1); // j % HW4
        float4 v = in[(size_t)(n * NC + c) * HW4 + hw4];
        s += (v.x + v.y) + (v.z + v.w);
        q += (v.x * v.x + v.y * v.y) + (v.z * v.z + v.w * v.w);
    }

    // warp reduce
    #pragma unroll
    for (int off = 16; off > 0; off >>= 1) {
        s += __shfl_down_sync(0xffffffffu, s, off);
        q += __shfl_down_sync(0xffffffffu, q, off);
    }

    __shared__ float sh_s[8], sh_q[8];
    const int lane = threadIdx.x & 31;
    const int wid  = threadIdx.x >> 5;
    if (lane == 0) { sh_s[wid] = s; sh_q[wid] = q; }
    __syncthreads();

    if (wid == 0) {
        const int nwarps = blockDim.x >> 5;
        s = (lane < nwarps) ? sh_s[lane] : 0.0f;
        q = (lane < nwarps) ? sh_q[lane] : 0.0f;
        #pragma unroll
        for (int off = 4; off > 0; off >>= 1) {
            s += __shfl_down_sync(0xffffffffu, s, off);
            q += __shfl_down_sync(0xffffffffu, q, off);
        }
        if (lane == 0) {
            atomicAdd(&g_sum[c], s);
            atomicAdd(&g_sq[c],  q);
        }
    }
}

__global__ void finalize_kernel() {
    int c = threadIdx.x;
    if (c < NC) {
        const float invN = 1.0f / (float)(PERCHAN4 * 4);
        float mean = g_sum[c] * invN;
        float var  = g_sq[c] * invN - mean * mean;
        g_mean[c] = mean;
        g_rstd[c] = rsqrtf(var + EPS);
    }
}

// 4 float4 per thread (MLP=4 to hide DRAM latency), fully coalesced.
__global__ void normalize_kernel(const float4* __restrict__ in,
                                 float4* __restrict__ out) {
    const int nthreads = gridDim.x * blockDim.x;
    int i = blockIdx.x * blockDim.x + threadIdx.x;

    #pragma unroll
    for (int k = 0; k < 4; k++, i += nthreads) {
        const int c = (i >> 14) & (NC - 1);   // (i / HW4) % NC
        const float mean = g_mean[c];
        const float rstd = g_rstd[c];
        float4 v = in[i];
        float4 o;
        o.x = (v.x - mean) * rstd;
        o.y = (v.y - mean) * rstd;
        o.z = (v.z - mean) * rstd;
        o.w = (v.w - mean) * rstd;
        out[i] = o;
    }
}

extern "C" void kernel_launch(void* const* d_in, const int* in_sizes, int n_in,
                              void* d_out, int out_size) {
    const float4* in  = (const float4*)d_in[0];
    float4*       out = (float4*)d_out;

    zero_acc_kernel<<<1, 64>>>();

    // 64 chunks x 64 channels, 256 threads: each thread covers 16 float4.
    dim3 rgrid(64, NC);
    reduce_kernel<<<rgrid, 256>>>(in);

    finalize_kernel<<<1, 64>>>();

    // TOTAL4 / (256 threads * 4 per-thread) = 16384 blocks
    normalize_kernel<<<TOTAL4 / (256 * 4), 256>>>(in, out);
}